// round 1
// baseline (speedup 1.0000x reference)
#include <cuda_runtime.h>
#include <cuda_bf16.h>
#include <math.h>

// ---------------------------------------------------------------------------
// 3-layer GCN: two GCNConv(64->64)+ReLU layers with symmetric normalization
// and self-loops, then Linear(64->16)+log_softmax.
// Outputs: [N*16] log_softmax, followed by [N*64] hidden h (relu of layer 2).
//
// Strategy:
//   - Build CSR (by dst) once per launch: histogram + 3-pass scan + atomic fill.
//   - Pre-scale GEMM outputs by dis[row]:  G = dis * (X @ W).
//   - Aggregate per node (pull, NO feature atomics):
//       S[i] = b + dis[i] * ( G[i] + sum_{e: dst=i} G[src_e] )
//   - Final fused kernel: relu -> 64x16 GEMM -> log_softmax, writes both outputs.
// ---------------------------------------------------------------------------

#define MAX_N 100000
#define MAX_E 1600000
#define NPAD  100352   // MAX_N rounded up

__device__ int   g_count[NPAD];
__device__ int   g_rowstart[NPAD];
__device__ int   g_cursor[NPAD];
__device__ float g_dis[NPAD];
__device__ int   g_bsum[1024];
__device__ int   g_esrc[MAX_E];
__device__ float g_G [MAX_N * 64];
__device__ float g_S1[MAX_N * 64];
__device__ float g_S2[MAX_N * 64];

// ---------------- CSR build ----------------

__global__ void k_init_count(int n) {
    int i = blockIdx.x * blockDim.x + threadIdx.x;
    if (i < n) g_count[i] = 0;
}

__global__ void k_count(const int* __restrict__ dst, int e) {
    int i = blockIdx.x * blockDim.x + threadIdx.x;
    if (i < e) atomicAdd(&g_count[dst[i]], 1);
}

// Pass 1: per-block (4096 elems) exclusive scan, block totals to g_bsum.
__global__ void k_scan1(int n) {
    __shared__ int sh[1024];
    int t = threadIdx.x;
    int base = blockIdx.x * 4096 + t * 4;
    int v0 = (base + 0 < n) ? g_count[base + 0] : 0;
    int v1 = (base + 1 < n) ? g_count[base + 1] : 0;
    int v2 = (base + 2 < n) ? g_count[base + 2] : 0;
    int v3 = (base + 3 < n) ? g_count[base + 3] : 0;
    int local = v0 + v1 + v2 + v3;
    sh[t] = local;
    __syncthreads();
    for (int off = 1; off < 1024; off <<= 1) {
        int x = (t >= off) ? sh[t - off] : 0;
        __syncthreads();
        sh[t] += x;
        __syncthreads();
    }
    int excl = sh[t] - local;
    if (t == 1023) g_bsum[blockIdx.x] = sh[1023];
    int run = excl;
    if (base + 0 < n) { g_rowstart[base + 0] = run; run += v0; }
    if (base + 1 < n) { g_rowstart[base + 1] = run; run += v1; }
    if (base + 2 < n) { g_rowstart[base + 2] = run; run += v2; }
    if (base + 3 < n) { g_rowstart[base + 3] = run; }
}

// Pass 2: single block scans the block totals (nb <= 1024).
__global__ void k_scan2(int nb) {
    __shared__ int sh[1024];
    int t = threadIdx.x;
    int v = (t < nb) ? g_bsum[t] : 0;
    sh[t] = v;
    __syncthreads();
    for (int off = 1; off < 1024; off <<= 1) {
        int x = (t >= off) ? sh[t - off] : 0;
        __syncthreads();
        sh[t] += x;
        __syncthreads();
    }
    if (t < nb) g_bsum[t] = sh[t] - v;   // exclusive offsets
}

// Pass 3: finalize rowstart, init cursors, compute dis = rsqrt(indeg+1).
__global__ void k_finalize(int n) {
    int i = blockIdx.x * blockDim.x + threadIdx.x;
    if (i >= n) return;
    int rs = g_rowstart[i] + g_bsum[i >> 12];
    g_rowstart[i] = rs;
    g_cursor[i]   = rs;
    g_dis[i]      = rsqrtf((float)(g_count[i] + 1));
}

__global__ void k_fill(const int* __restrict__ src, const int* __restrict__ dst, int e) {
    int i = blockIdx.x * blockDim.x + threadIdx.x;
    if (i >= e) return;
    int d = dst[i];
    int p = atomicAdd(&g_cursor[d], 1);
    g_esrc[p] = src[i];
}

// ---------------- GEMM 64x64: G[row] = dis[row] * (act(X[row]) @ W) ----------------
// Warp per row-stream; each lane owns output columns (lane, lane+32) with W
// columns cached in registers; row values broadcast via shfl.

__global__ void k_gemm64(const float* __restrict__ X, const float* __restrict__ W,
                         float* __restrict__ G, int n, int relu_in) {
    __shared__ float ws[4096];
    for (int i = threadIdx.x; i < 4096; i += blockDim.x) ws[i] = W[i];
    __syncthreads();

    int lane = threadIdx.x & 31;
    float w0[64], w1[64];
#pragma unroll
    for (int k = 0; k < 64; k++) {
        w0[k] = ws[k * 64 + lane];
        w1[k] = ws[k * 64 + lane + 32];
    }

    int warp   = (blockIdx.x * (blockDim.x >> 5)) + (threadIdx.x >> 5);
    int nwarps = gridDim.x * (blockDim.x >> 5);

    for (int row = warp; row < n; row += nwarps) {
        float x0 = X[row * 64 + lane];
        float x1 = X[row * 64 + 32 + lane];
        if (relu_in) { x0 = fmaxf(x0, 0.0f); x1 = fmaxf(x1, 0.0f); }
        float a0 = 0.0f, a1 = 0.0f;
#pragma unroll
        for (int k = 0; k < 32; k++) {
            float xv = __shfl_sync(0xffffffffu, x0, k);
            a0 = fmaf(xv, w0[k], a0);
            a1 = fmaf(xv, w1[k], a1);
        }
#pragma unroll
        for (int k = 0; k < 32; k++) {
            float xv = __shfl_sync(0xffffffffu, x1, k);
            a0 = fmaf(xv, w0[32 + k], a0);
            a1 = fmaf(xv, w1[32 + k], a1);
        }
        float d = g_dis[row];
        G[row * 64 + lane]      = a0 * d;
        G[row * 64 + 32 + lane] = a1 * d;
    }
}

// ---------------- Aggregation: S[i] = b + dis[i]*(G[i] + sum G[src]) ----------------
// 16 threads per node, one float4 feature chunk each.

__global__ void k_agg(const float* __restrict__ G, const float* __restrict__ bias,
                      float* __restrict__ S, int n) {
    int t = blockIdx.x * blockDim.x + threadIdx.x;
    int node = t >> 4;
    if (node >= n) return;
    int q = t & 15;

    const float4* Gv = (const float4*)G;
    float4 acc = Gv[(size_t)node * 16 + q];   // self-loop term g[i]

    int s = g_rowstart[node];
    int e = s + g_count[node];
    for (int p = s; p < e; p++) {
        int j = g_esrc[p];
        float4 v = Gv[(size_t)j * 16 + q];
        acc.x += v.x; acc.y += v.y; acc.z += v.z; acc.w += v.w;
    }
    float d  = g_dis[node];
    float4 b = ((const float4*)bias)[q];
    float4 o;
    o.x = fmaf(d, acc.x, b.x);
    o.y = fmaf(d, acc.y, b.y);
    o.z = fmaf(d, acc.z, b.z);
    o.w = fmaf(d, acc.w, b.w);
    ((float4*)S)[(size_t)node * 16 + q] = o;
}

// ---------------- Final: h = relu(S2); z = h@W3 + b3; log_softmax ----------------

__global__ void k_final(const float* __restrict__ S2, const float* __restrict__ W3,
                        const float* __restrict__ b3, float* __restrict__ out,
                        int n, int write_h) {
    __shared__ float w3s[64 * 16];
    __shared__ float b3s[16];
    for (int i = threadIdx.x; i < 64 * 16; i += blockDim.x) w3s[i] = W3[i];
    if (threadIdx.x < 16) b3s[threadIdx.x] = b3[threadIdx.x];
    __syncthreads();

    int row = blockIdx.x * blockDim.x + threadIdx.x;
    if (row >= n) return;

    float h[64];
    const float4* Sv = (const float4*)(S2 + (size_t)row * 64);
#pragma unroll
    for (int i = 0; i < 16; i++) {
        float4 v = Sv[i];
        h[4 * i + 0] = fmaxf(v.x, 0.0f);
        h[4 * i + 1] = fmaxf(v.y, 0.0f);
        h[4 * i + 2] = fmaxf(v.z, 0.0f);
        h[4 * i + 3] = fmaxf(v.w, 0.0f);
    }

    if (write_h) {
        float4* Hv = (float4*)(out + (size_t)n * 16 + (size_t)row * 64);
#pragma unroll
        for (int i = 0; i < 16; i++) {
            float4 v;
            v.x = h[4 * i + 0]; v.y = h[4 * i + 1];
            v.z = h[4 * i + 2]; v.w = h[4 * i + 3];
            Hv[i] = v;
        }
    }

    float z[16];
#pragma unroll
    for (int j = 0; j < 16; j++) z[j] = b3s[j];
#pragma unroll
    for (int k = 0; k < 64; k++) {
        float xv = h[k];
#pragma unroll
        for (int j = 0; j < 16; j++) z[j] = fmaf(xv, w3s[k * 16 + j], z[j]);
    }

    float m = z[0];
#pragma unroll
    for (int j = 1; j < 16; j++) m = fmaxf(m, z[j]);
    float ssum = 0.0f;
#pragma unroll
    for (int j = 0; j < 16; j++) ssum += expf(z[j] - m);
    float lse = m + logf(ssum);
#pragma unroll
    for (int j = 0; j < 16; j++) out[(size_t)row * 16 + j] = z[j] - lse;
}

// ---------------- launch ----------------

extern "C" void kernel_launch(void* const* d_in, const int* in_sizes, int n_in,
                              void* d_out, int out_size) {
    const float* x  = (const float*)d_in[0];
    const int*   ei = (const int*)d_in[1];
    const float* W1 = (const float*)d_in[2];
    const float* b1 = (const float*)d_in[3];
    const float* W2 = (const float*)d_in[4];
    const float* b2 = (const float*)d_in[5];
    const float* W3 = (const float*)d_in[6];
    const float* b3 = (const float*)d_in[7];
    float* out = (float*)d_out;

    int n = in_sizes[0] / 64;
    int e = in_sizes[1] / 2;
    const int* src = ei;
    const int* dst = ei + e;
    int write_h = (out_size >= n * 80) ? 1 : 0;

    float* G  = nullptr; cudaGetSymbolAddress((void**)&G,  g_G);
    float* S1 = nullptr; cudaGetSymbolAddress((void**)&S1, g_S1);
    float* S2 = nullptr; cudaGetSymbolAddress((void**)&S2, g_S2);

    int nb = (n + 4095) / 4096;

    k_init_count<<<(n + 255) / 256, 256>>>(n);
    k_count<<<(e + 255) / 256, 256>>>(dst, e);
    k_scan1<<<nb, 1024>>>(n);
    k_scan2<<<1, 1024>>>(nb);
    k_finalize<<<(n + 255) / 256, 256>>>(n);
    k_fill<<<(e + 255) / 256, 256>>>(src, dst, e);

    k_gemm64<<<592, 256>>>(x, W1, G, n, 0);
    k_agg<<<(n * 16 + 255) / 256, 256>>>(G, b1, S1, n);
    k_gemm64<<<592, 256>>>(S1, W2, G, n, 1);
    k_agg<<<(n * 16 + 255) / 256, 256>>>(G, b2, S2, n);
    k_final<<<(n + 255) / 256, 256>>>(S2, W3, b3, out, n, write_h);
}

// round 2
// speedup vs baseline: 1.1915x; 1.1915x over previous
#include <cuda_runtime.h>
#include <cuda_bf16.h>
#include <math.h>

// 3-layer GCN. Pull-style aggregation over a per-launch CSR (no feature atomics).
//   G = dis * (act(X) @ W)          [FFMA2-packed GEMM]
//   S[i] = b + dis[i] * (G[i] + sum_{dst=i} G[src])
//   out = log_softmax(relu(S2) @ W3 + b3), plus h = relu(S2)

#define MAX_N 100000
#define MAX_E 1600000
#define NPAD  100352

__device__ int   g_count[NPAD];
__device__ int   g_rowstart[NPAD];
__device__ int   g_cursor[NPAD];
__device__ float g_dis[NPAD];
__device__ int   g_sums[32];
__device__ int   g_flag[32];
__device__ int   g_esrc[MAX_E];
__device__ float g_G [MAX_N * 64];
__device__ float g_S1[MAX_N * 64];
__device__ float g_S2[MAX_N * 64];

typedef unsigned long long ull;

__device__ __forceinline__ void ffma2(ull& acc, ull x, ull w) {
    asm("fma.rn.f32x2 %0, %1, %2, %0;" : "+l"(acc) : "l"(x), "l"(w));
}
__device__ __forceinline__ ull pack_dup(float v) {
    ull r;
    asm("mov.b64 %0, {%1, %1};" : "=l"(r) : "r"(__float_as_uint(v)));
    return r;
}

// ---------------- CSR build ----------------

__global__ void k_count(const int* __restrict__ dst, int e) {
    int i4 = (blockIdx.x * blockDim.x + threadIdx.x) * 4;
    if (i4 + 3 < e) {
        int4 d = *(const int4*)&dst[i4];
        atomicAdd(&g_count[d.x], 1);
        atomicAdd(&g_count[d.y], 1);
        atomicAdd(&g_count[d.z], 1);
        atomicAdd(&g_count[d.w], 1);
    } else {
        for (int i = i4; i < e; i++) atomicAdd(&g_count[dst[i]], 1);
    }
}

// Single-kernel exclusive scan over counts (all nb<=25 blocks resident:
// publish block totals, every block sums all predecessors). Also writes
// rowstart / cursor / dis.
__global__ void k_scan(int n) {
    __shared__ int sh[1024];
    __shared__ int s_prev;
    int b = blockIdx.x, t = threadIdx.x;
    int base = b * 4096 + t * 4;
    int v0 = 0, v1 = 0, v2 = 0, v3 = 0;
    if (base + 3 < n) {
        int4 v = *(const int4*)&g_count[base];
        v0 = v.x; v1 = v.y; v2 = v.z; v3 = v.w;
    } else {
        if (base     < n) v0 = g_count[base];
        if (base + 1 < n) v1 = g_count[base + 1];
        if (base + 2 < n) v2 = g_count[base + 2];
    }
    int local = v0 + v1 + v2 + v3;
    sh[t] = local;
    __syncthreads();
    for (int off = 1; off < 1024; off <<= 1) {
        int x = (t >= off) ? sh[t - off] : 0;
        __syncthreads();
        sh[t] += x;
        __syncthreads();
    }
    if (t == 1023) {
        g_sums[b] = sh[1023];
        __threadfence();
        atomicExch(&g_flag[b], 1);
    }
    if (t < 32) {
        int p = 0;
        for (int i = t; i < b; i += 32) {
            while (atomicAdd(&g_flag[i], 0) == 0) { }
            p += atomicAdd(&g_sums[i], 0);
        }
#pragma unroll
        for (int o = 16; o; o >>= 1) p += __shfl_xor_sync(0xffffffffu, p, o);
        if (t == 0) s_prev = p;
    }
    int excl = sh[t] - local;
    __syncthreads();
    int run = s_prev + excl;
    if (base < n) {
        g_rowstart[base] = run; g_cursor[base] = run;
        g_dis[base] = rsqrtf((float)(v0 + 1)); run += v0;
    }
    if (base + 1 < n) {
        g_rowstart[base + 1] = run; g_cursor[base + 1] = run;
        g_dis[base + 1] = rsqrtf((float)(v1 + 1)); run += v1;
    }
    if (base + 2 < n) {
        g_rowstart[base + 2] = run; g_cursor[base + 2] = run;
        g_dis[base + 2] = rsqrtf((float)(v2 + 1)); run += v2;
    }
    if (base + 3 < n) {
        g_rowstart[base + 3] = run; g_cursor[base + 3] = run;
        g_dis[base + 3] = rsqrtf((float)(v3 + 1));
    }
}

__global__ void k_fill(const int* __restrict__ src, const int* __restrict__ dst, int e) {
    int i4 = (blockIdx.x * blockDim.x + threadIdx.x) * 4;
    if (i4 + 3 < e) {
        int4 s = *(const int4*)&src[i4];
        int4 d = *(const int4*)&dst[i4];
        g_esrc[atomicAdd(&g_cursor[d.x], 1)] = s.x;
        g_esrc[atomicAdd(&g_cursor[d.y], 1)] = s.y;
        g_esrc[atomicAdd(&g_cursor[d.z], 1)] = s.z;
        g_esrc[atomicAdd(&g_cursor[d.w], 1)] = s.w;
    } else {
        for (int i = i4; i < e; i++)
            g_esrc[atomicAdd(&g_cursor[dst[i]], 1)] = src[i];
    }
}

// ---------------- GEMM: G[row] = dis[row] * (act(X[row]) @ W) ----------------
// Lane owns packed column pair (2*lane, 2*lane+1); W rows as LDG.64 into 128
// regs; per-row x duplicated-pair staged in smem, broadcast via LDS.64; one
// fma.rn.f32x2 per k.

__global__ void __launch_bounds__(128, 1)
k_gemm64(const float* __restrict__ X, const float* __restrict__ W,
         float* __restrict__ G, int n, int relu_in) {
    __shared__ ull xs2[4 * 64];
    int lane = threadIdx.x & 31;
    int wid  = threadIdx.x >> 5;

    ull w2[64];
#pragma unroll
    for (int k = 0; k < 64; k++)
        w2[k] = ((const ull*)(W + k * 64))[lane];

    int warp   = blockIdx.x * 4 + wid;
    int nwarps = gridDim.x * 4;
    ull* xrow = &xs2[wid * 64];

    for (int row = warp; row < n; row += nwarps) {
        float x0 = X[row * 64 + lane];
        float x1 = X[row * 64 + 32 + lane];
        if (relu_in) { x0 = fmaxf(x0, 0.0f); x1 = fmaxf(x1, 0.0f); }
        xrow[lane]      = pack_dup(x0);
        xrow[lane + 32] = pack_dup(x1);
        __syncwarp();

        ull acc = 0;
#pragma unroll
        for (int k = 0; k < 64; k++)
            ffma2(acc, xrow[k], w2[k]);
        __syncwarp();

        float2 a = *reinterpret_cast<float2*>(&acc);
        float d = g_dis[row];
        float2 o; o.x = a.x * d; o.y = a.y * d;
        ((float2*)G)[(size_t)row * 32 + lane] = o;
    }
}

// ---------------- Aggregation: 1 warp per node, 2-edge ILP ----------------

__global__ void k_agg(const float* __restrict__ G, const float* __restrict__ bias,
                      float* __restrict__ S, int n) {
    int warp = (blockIdx.x * blockDim.x + threadIdx.x) >> 5;
    if (warp >= n) return;
    int node = warp;
    int lane = threadIdx.x & 31;
    int q  = lane & 15;
    int pe = lane >> 4;

    const float4* __restrict__ Gv = (const float4*)G;
    float4 acc = make_float4(0.f, 0.f, 0.f, 0.f);
    if (pe == 0) acc = Gv[(size_t)node * 16 + q];   // self-loop term

    int s   = g_rowstart[node];
    int cnt = g_count[node];
    int end = s + cnt;
    for (int p = s + pe; p < end; p += 2) {
        int j = g_esrc[p];
        float4 v = Gv[(size_t)j * 16 + q];
        acc.x += v.x; acc.y += v.y; acc.z += v.z; acc.w += v.w;
    }
    acc.x += __shfl_xor_sync(0xffffffffu, acc.x, 16);
    acc.y += __shfl_xor_sync(0xffffffffu, acc.y, 16);
    acc.z += __shfl_xor_sync(0xffffffffu, acc.z, 16);
    acc.w += __shfl_xor_sync(0xffffffffu, acc.w, 16);

    if (pe == 0) {
        float d  = g_dis[node];
        float4 b = ((const float4*)bias)[q];
        float4 o;
        o.x = fmaf(d, acc.x, b.x);
        o.y = fmaf(d, acc.y, b.y);
        o.z = fmaf(d, acc.z, b.z);
        o.w = fmaf(d, acc.w, b.w);
        ((float4*)S)[(size_t)node * 16 + q] = o;
    }
}

// ---------------- Final: h = relu(S2); z = h@W3 + b3; log_softmax ----------------

__global__ void k_final(const float* __restrict__ S2, const float* __restrict__ W3,
                        const float* __restrict__ b3, float* __restrict__ out,
                        int n, int write_h) {
    __shared__ float w3s[64 * 16];
    __shared__ float b3s[16];
    for (int i = threadIdx.x; i < 64 * 16; i += blockDim.x) w3s[i] = W3[i];
    if (threadIdx.x < 16) b3s[threadIdx.x] = b3[threadIdx.x];
    __syncthreads();

    int row = blockIdx.x * blockDim.x + threadIdx.x;
    if (row >= n) return;

    float h[64];
    const float4* Sv = (const float4*)(S2 + (size_t)row * 64);
#pragma unroll
    for (int i = 0; i < 16; i++) {
        float4 v = Sv[i];
        h[4 * i + 0] = fmaxf(v.x, 0.0f);
        h[4 * i + 1] = fmaxf(v.y, 0.0f);
        h[4 * i + 2] = fmaxf(v.z, 0.0f);
        h[4 * i + 3] = fmaxf(v.w, 0.0f);
    }

    if (write_h) {
        float4* Hv = (float4*)(out + (size_t)n * 16 + (size_t)row * 64);
#pragma unroll
        for (int i = 0; i < 16; i++) {
            float4 v;
            v.x = h[4 * i + 0]; v.y = h[4 * i + 1];
            v.z = h[4 * i + 2]; v.w = h[4 * i + 3];
            Hv[i] = v;
        }
    }

    float z[16];
#pragma unroll
    for (int j = 0; j < 16; j++) z[j] = b3s[j];
#pragma unroll
    for (int k = 0; k < 64; k++) {
        float xv = h[k];
#pragma unroll
        for (int j = 0; j < 16; j++) z[j] = fmaf(xv, w3s[k * 16 + j], z[j]);
    }

    float m = z[0];
#pragma unroll
    for (int j = 1; j < 16; j++) m = fmaxf(m, z[j]);
    float ssum = 0.0f;
#pragma unroll
    for (int j = 0; j < 16; j++) ssum += __expf(z[j] - m);
    float lse = m + __logf(ssum);
#pragma unroll
    for (int j = 0; j < 16; j++) out[(size_t)row * 16 + j] = z[j] - lse;
}

// ---------------- launch ----------------

extern "C" void kernel_launch(void* const* d_in, const int* in_sizes, int n_in,
                              void* d_out, int out_size) {
    const float* x  = (const float*)d_in[0];
    const int*   ei = (const int*)d_in[1];
    const float* W1 = (const float*)d_in[2];
    const float* b1 = (const float*)d_in[3];
    const float* W2 = (const float*)d_in[4];
    const float* b2 = (const float*)d_in[5];
    const float* W3 = (const float*)d_in[6];
    const float* b3 = (const float*)d_in[7];
    float* out = (float*)d_out;

    int n = in_sizes[0] / 64;
    int e = in_sizes[1] / 2;
    const int* src = ei;
    const int* dst = ei + e;
    int write_h = (out_size >= n * 80) ? 1 : 0;

    void* cnt_p;  cudaGetSymbolAddress(&cnt_p,  g_count);
    void* flag_p; cudaGetSymbolAddress(&flag_p, g_flag);
    float* G  = nullptr; cudaGetSymbolAddress((void**)&G,  g_G);
    float* S1 = nullptr; cudaGetSymbolAddress((void**)&S1, g_S1);
    float* S2 = nullptr; cudaGetSymbolAddress((void**)&S2, g_S2);

    int nb = (n + 4095) / 4096;
    int e4blocks = ((e + 3) / 4 + 255) / 256;

    cudaMemsetAsync(cnt_p,  0, (size_t)n * sizeof(int));
    cudaMemsetAsync(flag_p, 0, 32 * sizeof(int));
    k_count<<<e4blocks, 256>>>(dst, e);
    k_scan<<<nb, 1024>>>(n);
    k_fill<<<e4blocks, 256>>>(src, dst, e);

    k_gemm64<<<444, 128>>>(x, W1, G, n, 0);
    k_agg<<<(n * 32 + 255) / 256, 256>>>(G, b1, S1, n);
    k_gemm64<<<444, 128>>>(S1, W2, G, n, 1);
    k_agg<<<(n * 32 + 255) / 256, 256>>>(G, b2, S2, n);
    k_final<<<(n + 255) / 256, 256>>>(S2, W3, b3, out, n, write_h);
}

// round 3
// speedup vs baseline: 1.2814x; 1.0755x over previous
#include <cuda_runtime.h>
#include <cuda_bf16.h>
#include <math.h>

// 3-layer GCN. Pull-style aggregation over a per-launch CSR (no feature atomics).
//   G = dis * (act(X) @ W)          [tiled FFMA2 GEMM, 8-row ILP]
//   S[i] = b + dis[i] * (G[i] + sum_{dst=i} G[src])
//   out = log_softmax(relu(S2) @ W3 + b3), plus h = relu(S2)

#define MAX_N 100000
#define MAX_E 1600000
#define NPAD  100352

__device__ int   g_count[NPAD];
__device__ int   g_rowstart[NPAD];
__device__ int   g_cursor[NPAD];
__device__ float g_dis[NPAD];
__device__ int   g_sums[32];
__device__ int   g_flag[32];
__device__ int   g_esrc[MAX_E];
__device__ float g_G [MAX_N * 64];
__device__ float g_S1[MAX_N * 64];
__device__ float g_S2[MAX_N * 64];

typedef unsigned long long ull;

__device__ __forceinline__ void ffma2(ull& acc, ull x, ull w) {
    asm("fma.rn.f32x2 %0, %1, %2, %0;" : "+l"(acc) : "l"(x), "l"(w));
}
__device__ __forceinline__ ull pack_dup(float v) {
    ull r;
    asm("mov.b64 %0, {%1, %1};" : "=l"(r) : "r"(__float_as_uint(v)));
    return r;
}

// ---------------- CSR build ----------------

__global__ void k_count(const int* __restrict__ dst, int e) {
    int i4 = (blockIdx.x * blockDim.x + threadIdx.x) * 4;
    if (i4 + 3 < e) {
        int4 d = *(const int4*)&dst[i4];
        atomicAdd(&g_count[d.x], 1);
        atomicAdd(&g_count[d.y], 1);
        atomicAdd(&g_count[d.z], 1);
        atomicAdd(&g_count[d.w], 1);
    } else {
        for (int i = i4; i < e; i++) atomicAdd(&g_count[dst[i]], 1);
    }
}

// Single-kernel exclusive scan over counts (all nb<=25 blocks resident).
// Also writes rowstart / cursor / dis.
__global__ void k_scan(int n) {
    __shared__ int sh[1024];
    __shared__ int s_prev;
    int b = blockIdx.x, t = threadIdx.x;
    int base = b * 4096 + t * 4;
    int v0 = 0, v1 = 0, v2 = 0, v3 = 0;
    if (base + 3 < n) {
        int4 v = *(const int4*)&g_count[base];
        v0 = v.x; v1 = v.y; v2 = v.z; v3 = v.w;
    } else {
        if (base     < n) v0 = g_count[base];
        if (base + 1 < n) v1 = g_count[base + 1];
        if (base + 2 < n) v2 = g_count[base + 2];
    }
    int local = v0 + v1 + v2 + v3;
    sh[t] = local;
    __syncthreads();
    for (int off = 1; off < 1024; off <<= 1) {
        int x = (t >= off) ? sh[t - off] : 0;
        __syncthreads();
        sh[t] += x;
        __syncthreads();
    }
    if (t == 1023) {
        g_sums[b] = sh[1023];
        __threadfence();
        atomicExch(&g_flag[b], 1);
    }
    if (t < 32) {
        int p = 0;
        for (int i = t; i < b; i += 32) {
            while (atomicAdd(&g_flag[i], 0) == 0) { }
            p += atomicAdd(&g_sums[i], 0);
        }
#pragma unroll
        for (int o = 16; o; o >>= 1) p += __shfl_xor_sync(0xffffffffu, p, o);
        if (t == 0) s_prev = p;
    }
    int excl = sh[t] - local;
    __syncthreads();
    int run = s_prev + excl;
    if (base < n) {
        g_rowstart[base] = run; g_cursor[base] = run;
        g_dis[base] = rsqrtf((float)(v0 + 1)); run += v0;
    }
    if (base + 1 < n) {
        g_rowstart[base + 1] = run; g_cursor[base + 1] = run;
        g_dis[base + 1] = rsqrtf((float)(v1 + 1)); run += v1;
    }
    if (base + 2 < n) {
        g_rowstart[base + 2] = run; g_cursor[base + 2] = run;
        g_dis[base + 2] = rsqrtf((float)(v2 + 1)); run += v2;
    }
    if (base + 3 < n) {
        g_rowstart[base + 3] = run; g_cursor[base + 3] = run;
        g_dis[base + 3] = rsqrtf((float)(v3 + 1));
    }
}

__global__ void k_fill(const int* __restrict__ src, const int* __restrict__ dst, int e) {
    int i4 = (blockIdx.x * blockDim.x + threadIdx.x) * 4;
    if (i4 + 3 < e) {
        int4 s = *(const int4*)&src[i4];
        int4 d = *(const int4*)&dst[i4];
        g_esrc[atomicAdd(&g_cursor[d.x], 1)] = s.x;
        g_esrc[atomicAdd(&g_cursor[d.y], 1)] = s.y;
        g_esrc[atomicAdd(&g_cursor[d.z], 1)] = s.z;
        g_esrc[atomicAdd(&g_cursor[d.w], 1)] = s.w;
    } else {
        for (int i = i4; i < e; i++)
            g_esrc[atomicAdd(&g_cursor[dst[i]], 1)] = src[i];
    }
}

// ---------------- GEMM: G[row] = dis[row] * (act(X[row]) @ W) ----------------
// Tiled: block of 256 threads processes 64-row tiles. X tile staged in smem
// pre-duplicated as {x,x} f32x2 pairs; W staged once as column-pair ulls.
// Thread (warp w, lane c) computes rows w*8..w*8+7, columns (2c, 2c+1):
// 8 independent FFMA2 accumulator chains.

__global__ void __launch_bounds__(256)
k_gemm64(const float* __restrict__ X, const float* __restrict__ W,
         float* __restrict__ G, int n, int relu_in) {
    __shared__ ull ws2[64 * 32];   // 16 KB  ws2[k*32 + c]
    __shared__ ull xs2[64 * 64];   // 32 KB  xs2[r*64 + k]  ({x,x} dup'd)

    int tid  = threadIdx.x;
    int lane = tid & 31;
    int wid  = tid >> 5;

    // Stage W once (W row-major 64x64: ull at [k*32+c] = cols (2c,2c+1) of row k)
    const ull* Wv = (const ull*)W;
    for (int i = tid; i < 2048; i += 256) ws2[i] = Wv[i];

    int ntiles = (n + 63) >> 6;
    const float4* Xv = (const float4*)X;

    for (int tile = blockIdx.x; tile < ntiles; tile += gridDim.x) {
        __syncthreads();
        // Stage X tile (64 rows x 16 float4), relu + duplicate
        int rowbase = tile << 6;
#pragma unroll
        for (int i = tid; i < 1024; i += 256) {
            int r  = i >> 4;
            int kg = i & 15;
            int row = rowbase + r;
            float4 v = make_float4(0.f, 0.f, 0.f, 0.f);
            if (row < n) v = Xv[(size_t)row * 16 + kg];
            if (relu_in) {
                v.x = fmaxf(v.x, 0.f); v.y = fmaxf(v.y, 0.f);
                v.z = fmaxf(v.z, 0.f); v.w = fmaxf(v.w, 0.f);
            }
            ulonglong2* dst0 = (ulonglong2*)&xs2[r * 64 + kg * 4];
            ulonglong2 p0; p0.x = pack_dup(v.x); p0.y = pack_dup(v.y);
            ulonglong2 p1; p1.x = pack_dup(v.z); p1.y = pack_dup(v.w);
            dst0[0] = p0;
            dst0[1] = p1;
        }
        __syncthreads();

        ull acc[8];
#pragma unroll
        for (int r = 0; r < 8; r++) acc[r] = 0;

        int r0 = wid * 8;
#pragma unroll
        for (int kg = 0; kg < 16; kg++) {
            ull w0 = ws2[(kg * 4 + 0) * 32 + lane];
            ull w1 = ws2[(kg * 4 + 1) * 32 + lane];
            ull w2 = ws2[(kg * 4 + 2) * 32 + lane];
            ull w3 = ws2[(kg * 4 + 3) * 32 + lane];
#pragma unroll
            for (int r = 0; r < 8; r++) {
                const ulonglong2* xp = (const ulonglong2*)&xs2[(r0 + r) * 64 + kg * 4];
                ulonglong2 xa = xp[0];
                ulonglong2 xb = xp[1];
                ffma2(acc[r], xa.x, w0);
                ffma2(acc[r], xa.y, w1);
                ffma2(acc[r], xb.x, w2);
                ffma2(acc[r], xb.y, w3);
            }
        }

#pragma unroll
        for (int r = 0; r < 8; r++) {
            int row = rowbase + r0 + r;
            if (row < n) {
                float2 a = *reinterpret_cast<float2*>(&acc[r]);
                float d = g_dis[row];
                float2 o; o.x = a.x * d; o.y = a.y * d;
                ((float2*)G)[(size_t)row * 32 + lane] = o;
            }
        }
    }
}

// ---------------- Aggregation: 1 warp per node, 2-edge ILP ----------------

__global__ void k_agg(const float* __restrict__ G, const float* __restrict__ bias,
                      float* __restrict__ S, int n) {
    int warp = (blockIdx.x * blockDim.x + threadIdx.x) >> 5;
    if (warp >= n) return;
    int node = warp;
    int lane = threadIdx.x & 31;
    int q  = lane & 15;
    int pe = lane >> 4;

    const float4* __restrict__ Gv = (const float4*)G;
    float4 acc = make_float4(0.f, 0.f, 0.f, 0.f);
    if (pe == 0) acc = Gv[(size_t)node * 16 + q];   // self-loop term

    int s   = g_rowstart[node];
    int cnt = g_count[node];
    int end = s + cnt;
    for (int p = s + pe; p < end; p += 2) {
        int j = g_esrc[p];
        float4 v = Gv[(size_t)j * 16 + q];
        acc.x += v.x; acc.y += v.y; acc.z += v.z; acc.w += v.w;
    }
    acc.x += __shfl_xor_sync(0xffffffffu, acc.x, 16);
    acc.y += __shfl_xor_sync(0xffffffffu, acc.y, 16);
    acc.z += __shfl_xor_sync(0xffffffffu, acc.z, 16);
    acc.w += __shfl_xor_sync(0xffffffffu, acc.w, 16);

    if (pe == 0) {
        float d  = g_dis[node];
        float4 b = ((const float4*)bias)[q];
        float4 o;
        o.x = fmaf(d, acc.x, b.x);
        o.y = fmaf(d, acc.y, b.y);
        o.z = fmaf(d, acc.z, b.z);
        o.w = fmaf(d, acc.w, b.w);
        ((float4*)S)[(size_t)node * 16 + q] = o;
    }
}

// ---------------- Final: h = relu(S2); z = h@W3 + b3; log_softmax ----------------

__global__ void k_final(const float* __restrict__ S2, const float* __restrict__ W3,
                        const float* __restrict__ b3, float* __restrict__ out,
                        int n, int write_h) {
    __shared__ float w3s[64 * 16];
    __shared__ float b3s[16];
    for (int i = threadIdx.x; i < 64 * 16; i += blockDim.x) w3s[i] = W3[i];
    if (threadIdx.x < 16) b3s[threadIdx.x] = b3[threadIdx.x];
    __syncthreads();

    int row = blockIdx.x * blockDim.x + threadIdx.x;
    if (row >= n) return;

    float h[64];
    const float4* Sv = (const float4*)(S2 + (size_t)row * 64);
#pragma unroll
    for (int i = 0; i < 16; i++) {
        float4 v = Sv[i];
        h[4 * i + 0] = fmaxf(v.x, 0.0f);
        h[4 * i + 1] = fmaxf(v.y, 0.0f);
        h[4 * i + 2] = fmaxf(v.z, 0.0f);
        h[4 * i + 3] = fmaxf(v.w, 0.0f);
    }

    if (write_h) {
        float4* Hv = (float4*)(out + (size_t)n * 16 + (size_t)row * 64);
#pragma unroll
        for (int i = 0; i < 16; i++) {
            float4 v;
            v.x = h[4 * i + 0]; v.y = h[4 * i + 1];
            v.z = h[4 * i + 2]; v.w = h[4 * i + 3];
            Hv[i] = v;
        }
    }

    float z[16];
#pragma unroll
    for (int j = 0; j < 16; j++) z[j] = b3s[j];
#pragma unroll
    for (int k = 0; k < 64; k++) {
        float xv = h[k];
#pragma unroll
        for (int j = 0; j < 16; j++) z[j] = fmaf(xv, w3s[k * 16 + j], z[j]);
    }

    float m = z[0];
#pragma unroll
    for (int j = 1; j < 16; j++) m = fmaxf(m, z[j]);
    float ssum = 0.0f;
#pragma unroll
    for (int j = 0; j < 16; j++) ssum += __expf(z[j] - m);
    float lse = m + __logf(ssum);
#pragma unroll
    for (int j = 0; j < 16; j++) out[(size_t)row * 16 + j] = z[j] - lse;
}

// ---------------- launch ----------------

extern "C" void kernel_launch(void* const* d_in, const int* in_sizes, int n_in,
                              void* d_out, int out_size) {
    const float* x  = (const float*)d_in[0];
    const int*   ei = (const int*)d_in[1];
    const float* W1 = (const float*)d_in[2];
    const float* b1 = (const float*)d_in[3];
    const float* W2 = (const float*)d_in[4];
    const float* b2 = (const float*)d_in[5];
    const float* W3 = (const float*)d_in[6];
    const float* b3 = (const float*)d_in[7];
    float* out = (float*)d_out;

    int n = in_sizes[0] / 64;
    int e = in_sizes[1] / 2;
    const int* src = ei;
    const int* dst = ei + e;
    int write_h = (out_size >= n * 80) ? 1 : 0;

    void* cnt_p;  cudaGetSymbolAddress(&cnt_p,  g_count);
    void* flag_p; cudaGetSymbolAddress(&flag_p, g_flag);
    float* G  = nullptr; cudaGetSymbolAddress((void**)&G,  g_G);
    float* S1 = nullptr; cudaGetSymbolAddress((void**)&S1, g_S1);
    float* S2 = nullptr; cudaGetSymbolAddress((void**)&S2, g_S2);

    int nb = (n + 4095) / 4096;
    int e4blocks = ((e + 3) / 4 + 255) / 256;

    cudaMemsetAsync(cnt_p,  0, (size_t)n * sizeof(int));
    cudaMemsetAsync(flag_p, 0, 32 * sizeof(int));
    k_count<<<e4blocks, 256>>>(dst, e);
    k_scan<<<nb, 1024>>>(n);
    k_fill<<<e4blocks, 256>>>(src, dst, e);

    k_gemm64<<<592, 256>>>(x, W1, G, n, 0);
    k_agg<<<(n * 32 + 255) / 256, 256>>>(G, b1, S1, n);
    k_gemm64<<<592, 256>>>(S1, W2, G, n, 1);
    k_agg<<<(n * 32 + 255) / 256, 256>>>(G, b2, S2, n);
    k_final<<<(n + 255) / 256, 256>>>(S2, W3, b3, out, n, write_h);
}

// round 4
// speedup vs baseline: 1.3290x; 1.0371x over previous
#include <cuda_runtime.h>
#include <cuda_fp16.h>
#include <math.h>

// 3-layer GCN. Pull-style aggregation over a per-launch CSR (no feature atomics).
//   G(half) = (dis * act(X)) @ W      [row-pair f32x2 GEMM, W dup'd in smem]
//   S[i] = b + dis[i] * (G[i] + sum_{dst=i} G[src])   (fp32 accum)
//   out = log_softmax(relu(S2) @ W3 + b3), plus h = relu(S2)

#define MAX_N 100000
#define MAX_E 1600000
#define NPAD  100352

__device__ int    g_count[NPAD];
__device__ int    g_rowstart[NPAD];
__device__ int    g_cursor[NPAD];
__device__ float  g_dis[NPAD];
__device__ int    g_sums[32];
__device__ int    g_flag[32];
__device__ int    g_esrc[MAX_E];
__device__ __half g_Gh[MAX_N * 64];
__device__ float  g_S1[MAX_N * 64];
__device__ float  g_S2[MAX_N * 64];

typedef unsigned long long ull;

__device__ __forceinline__ void ffma2(ull& acc, ull x, ull w) {
    asm("fma.rn.f32x2 %0, %1, %2, %0;" : "+l"(acc) : "l"(x), "l"(w));
}
__device__ __forceinline__ void fadd2(ull& a, ull b) {
    asm("add.rn.f32x2 %0, %0, %1;" : "+l"(a) : "l"(b));
}
__device__ __forceinline__ ull pack_dup(float v) {
    ull r;
    asm("mov.b64 %0, {%1, %1};" : "=l"(r) : "r"(__float_as_uint(v)));
    return r;
}
__device__ __forceinline__ ull h2_to_f2(unsigned int h) {
    __half2 hh = *reinterpret_cast<__half2*>(&h);
    float2 f = __half22float2(hh);
    return *reinterpret_cast<ull*>(&f);
}

// ---------------- CSR build ----------------

__global__ void k_count(const int* __restrict__ dst, int e) {
    int i4 = (blockIdx.x * blockDim.x + threadIdx.x) * 4;
    if (i4 + 3 < e) {
        int4 d = *(const int4*)&dst[i4];
        atomicAdd(&g_count[d.x], 1);
        atomicAdd(&g_count[d.y], 1);
        atomicAdd(&g_count[d.z], 1);
        atomicAdd(&g_count[d.w], 1);
    } else {
        for (int i = i4; i < e; i++) atomicAdd(&g_count[dst[i]], 1);
    }
}

// Single-kernel exclusive scan over counts (all nb<=25 blocks resident).
__global__ void k_scan(int n) {
    __shared__ int sh[1024];
    __shared__ int s_prev;
    int b = blockIdx.x, t = threadIdx.x;
    int base = b * 4096 + t * 4;
    int v0 = 0, v1 = 0, v2 = 0, v3 = 0;
    if (base + 3 < n) {
        int4 v = *(const int4*)&g_count[base];
        v0 = v.x; v1 = v.y; v2 = v.z; v3 = v.w;
    } else {
        if (base     < n) v0 = g_count[base];
        if (base + 1 < n) v1 = g_count[base + 1];
        if (base + 2 < n) v2 = g_count[base + 2];
    }
    int local = v0 + v1 + v2 + v3;
    sh[t] = local;
    __syncthreads();
    for (int off = 1; off < 1024; off <<= 1) {
        int x = (t >= off) ? sh[t - off] : 0;
        __syncthreads();
        sh[t] += x;
        __syncthreads();
    }
    if (t == 1023) {
        g_sums[b] = sh[1023];
        __threadfence();
        atomicExch(&g_flag[b], 1);
    }
    if (t < 32) {
        int p = 0;
        for (int i = t; i < b; i += 32) {
            while (atomicAdd(&g_flag[i], 0) == 0) { }
            p += atomicAdd(&g_sums[i], 0);
        }
#pragma unroll
        for (int o = 16; o; o >>= 1) p += __shfl_xor_sync(0xffffffffu, p, o);
        if (t == 0) s_prev = p;
    }
    int excl = sh[t] - local;
    __syncthreads();
    int run = s_prev + excl;
    if (base < n) {
        g_rowstart[base] = run; g_cursor[base] = run;
        g_dis[base] = rsqrtf((float)(v0 + 1)); run += v0;
    }
    if (base + 1 < n) {
        g_rowstart[base + 1] = run; g_cursor[base + 1] = run;
        g_dis[base + 1] = rsqrtf((float)(v1 + 1)); run += v1;
    }
    if (base + 2 < n) {
        g_rowstart[base + 2] = run; g_cursor[base + 2] = run;
        g_dis[base + 2] = rsqrtf((float)(v2 + 1)); run += v2;
    }
    if (base + 3 < n) {
        g_rowstart[base + 3] = run; g_cursor[base + 3] = run;
        g_dis[base + 3] = rsqrtf((float)(v3 + 1));
    }
}

__global__ void k_fill(const int* __restrict__ src, const int* __restrict__ dst, int e) {
    int i4 = (blockIdx.x * blockDim.x + threadIdx.x) * 4;
    if (i4 + 3 < e) {
        int4 s = *(const int4*)&src[i4];
        int4 d = *(const int4*)&dst[i4];
        g_esrc[atomicAdd(&g_cursor[d.x], 1)] = s.x;
        g_esrc[atomicAdd(&g_cursor[d.y], 1)] = s.y;
        g_esrc[atomicAdd(&g_cursor[d.z], 1)] = s.z;
        g_esrc[atomicAdd(&g_cursor[d.w], 1)] = s.w;
    } else {
        for (int i = i4; i < e; i++)
            g_esrc[atomicAdd(&g_cursor[dst[i]], 1)] = src[i];
    }
}

// ---------------- GEMM: G(half)[row] = (dis[row]*act(X[row])) @ W ----------------
// f32x2 pair = 2 adjacent ROWS. W duplicated {w,w} in smem once per kernel;
// X staged transposed (xst[k][r], dis-scaled) so row-pairs are adjacent floats.
// Thread: warp wid owns rows wid*8..wid*8+7 (4 pairs); lane owns cols (2l, 2l+1).
// Inner loop per k: 3 LDS.128 + 8 FFMA2 (x loads warp-broadcast).

__global__ void __launch_bounds__(256)
k_gemm64(const float* __restrict__ X, const float* __restrict__ W,
         __half* __restrict__ G, int n, int relu_in) {
    __shared__ ull   wsd[64 * 64];   // 32 KB  wsd[k*64 + c] = {W[k][c], W[k][c]}
    __shared__ float xst[64 * 64];   // 16 KB  xst[k*64 + r]

    int tid  = threadIdx.x;
    int lane = tid & 31;
    int wid  = tid >> 5;

    for (int i = tid; i < 4096; i += 256) wsd[i] = pack_dup(W[i]);

    int ntiles = (n + 63) >> 6;
    const float4* Xv = (const float4*)X;
    int r0 = wid * 8;

    for (int tile = blockIdx.x; tile < ntiles; tile += gridDim.x) {
        __syncthreads();
        int rowbase = tile << 6;
        // Stage X tile transposed + relu + dis-scale.
        // i -> (r = i&63, kgroup = i>>6): warp writes 32 consecutive r (no conflicts).
#pragma unroll
        for (int j = 0; j < 4; j++) {
            int i  = tid + j * 256;
            int r  = i & 63;
            int kg = i >> 6;
            int row = rowbase + r;
            float4 v = make_float4(0.f, 0.f, 0.f, 0.f);
            float d = 0.f;
            if (row < n) { v = Xv[(size_t)row * 16 + kg]; d = g_dis[row]; }
            if (relu_in) {
                v.x = fmaxf(v.x, 0.f); v.y = fmaxf(v.y, 0.f);
                v.z = fmaxf(v.z, 0.f); v.w = fmaxf(v.w, 0.f);
            }
            xst[(4 * kg + 0) * 64 + r] = v.x * d;
            xst[(4 * kg + 1) * 64 + r] = v.y * d;
            xst[(4 * kg + 2) * 64 + r] = v.z * d;
            xst[(4 * kg + 3) * 64 + r] = v.w * d;
        }
        __syncthreads();

        ull a00 = 0, a01 = 0, a10 = 0, a11 = 0, a20 = 0, a21 = 0, a30 = 0, a31 = 0;
#pragma unroll 16
        for (int k = 0; k < 64; k++) {
            ulonglong2 xa = *(const ulonglong2*)&xst[k * 64 + r0];
            ulonglong2 xb = *(const ulonglong2*)&xst[k * 64 + r0 + 4];
            ulonglong2 w  = *(const ulonglong2*)&wsd[k * 64 + 2 * lane];
            ffma2(a00, xa.x, w.x); ffma2(a01, xa.x, w.y);
            ffma2(a10, xa.y, w.x); ffma2(a11, xa.y, w.y);
            ffma2(a20, xb.x, w.x); ffma2(a21, xb.x, w.y);
            ffma2(a30, xb.y, w.x); ffma2(a31, xb.y, w.y);
        }

        ull ac[4][2] = {{a00, a01}, {a10, a11}, {a20, a21}, {a30, a31}};
        __half2* Gv = (__half2*)G;
#pragma unroll
        for (int rp = 0; rp < 4; rp++) {
            float2 c0 = *reinterpret_cast<float2*>(&ac[rp][0]);
            float2 c1 = *reinterpret_cast<float2*>(&ac[rp][1]);
            int re = rowbase + r0 + 2 * rp;
            if (re < n)     Gv[(size_t)re * 32 + lane]       = __floats2half2_rn(c0.x, c1.x);
            if (re + 1 < n) Gv[(size_t)(re + 1) * 32 + lane] = __floats2half2_rn(c0.y, c1.y);
        }
    }
}

// ---------------- Aggregation: 1 warp/node; 8 lanes x 16B, 4-edge ILP ----------------

__global__ void k_agg(const __half* __restrict__ G, const float* __restrict__ bias,
                      float* __restrict__ S, int n) {
    int warp = (blockIdx.x * blockDim.x + threadIdx.x) >> 5;
    if (warp >= n) return;
    int node = warp;
    int lane = threadIdx.x & 31;
    int q  = lane & 7;    // 16-byte feature chunk (8 halves)
    int pe = lane >> 3;   // 0..3 edge phase

    const uint4* __restrict__ Gv = (const uint4*)G;
    ull acc0 = 0, acc1 = 0, acc2 = 0, acc3 = 0;

    if (pe == 0) {
        uint4 v = Gv[(size_t)node * 8 + q];   // self-loop term
        acc0 = h2_to_f2(v.x); acc1 = h2_to_f2(v.y);
        acc2 = h2_to_f2(v.z); acc3 = h2_to_f2(v.w);
    }

    int s   = g_rowstart[node];
    int end = s + g_count[node];
    for (int p = s + pe; p < end; p += 4) {
        int j = g_esrc[p];
        uint4 v = Gv[(size_t)j * 8 + q];
        fadd2(acc0, h2_to_f2(v.x));
        fadd2(acc1, h2_to_f2(v.y));
        fadd2(acc2, h2_to_f2(v.z));
        fadd2(acc3, h2_to_f2(v.w));
    }

#pragma unroll
    for (int o = 8; o <= 16; o <<= 1) {
        fadd2(acc0, __shfl_xor_sync(0xffffffffu, acc0, o));
        fadd2(acc1, __shfl_xor_sync(0xffffffffu, acc1, o));
        fadd2(acc2, __shfl_xor_sync(0xffffffffu, acc2, o));
        fadd2(acc3, __shfl_xor_sync(0xffffffffu, acc3, o));
    }

    if (pe == 0) {
        float d = g_dis[node];
        float2 f0 = *reinterpret_cast<float2*>(&acc0);
        float2 f1 = *reinterpret_cast<float2*>(&acc1);
        float2 f2 = *reinterpret_cast<float2*>(&acc2);
        float2 f3 = *reinterpret_cast<float2*>(&acc3);
        const float4* Bv = (const float4*)bias;
        float4 b0 = Bv[q * 2], b1 = Bv[q * 2 + 1];
        float4 o0, o1;
        o0.x = fmaf(d, f0.x, b0.x); o0.y = fmaf(d, f0.y, b0.y);
        o0.z = fmaf(d, f1.x, b0.z); o0.w = fmaf(d, f1.y, b0.w);
        o1.x = fmaf(d, f2.x, b1.x); o1.y = fmaf(d, f2.y, b1.y);
        o1.z = fmaf(d, f3.x, b1.z); o1.w = fmaf(d, f3.y, b1.w);
        float4* Sv = (float4*)S;
        Sv[(size_t)node * 16 + q * 2]     = o0;
        Sv[(size_t)node * 16 + q * 2 + 1] = o1;
    }
}

// ---------------- Final: h = relu(S2); z = h@W3 + b3; log_softmax ----------------

__global__ void k_final(const float* __restrict__ S2, const float* __restrict__ W3,
                        const float* __restrict__ b3, float* __restrict__ out,
                        int n, int write_h) {
    __shared__ float w3s[64 * 16];
    __shared__ float b3s[16];
    for (int i = threadIdx.x; i < 64 * 16; i += blockDim.x) w3s[i] = W3[i];
    if (threadIdx.x < 16) b3s[threadIdx.x] = b3[threadIdx.x];
    __syncthreads();

    int row = blockIdx.x * blockDim.x + threadIdx.x;
    if (row >= n) return;

    float h[64];
    const float4* Sv = (const float4*)(S2 + (size_t)row * 64);
#pragma unroll
    for (int i = 0; i < 16; i++) {
        float4 v = Sv[i];
        h[4 * i + 0] = fmaxf(v.x, 0.0f);
        h[4 * i + 1] = fmaxf(v.y, 0.0f);
        h[4 * i + 2] = fmaxf(v.z, 0.0f);
        h[4 * i + 3] = fmaxf(v.w, 0.0f);
    }

    if (write_h) {
        float4* Hv = (float4*)(out + (size_t)n * 16 + (size_t)row * 64);
#pragma unroll
        for (int i = 0; i < 16; i++) {
            float4 v;
            v.x = h[4 * i + 0]; v.y = h[4 * i + 1];
            v.z = h[4 * i + 2]; v.w = h[4 * i + 3];
            Hv[i] = v;
        }
    }

    float z[16];
#pragma unroll
    for (int j = 0; j < 16; j++) z[j] = b3s[j];
#pragma unroll
    for (int k = 0; k < 64; k++) {
        float xv = h[k];
#pragma unroll
        for (int j = 0; j < 16; j++) z[j] = fmaf(xv, w3s[k * 16 + j], z[j]);
    }

    float m = z[0];
#pragma unroll
    for (int j = 1; j < 16; j++) m = fmaxf(m, z[j]);
    float ssum = 0.0f;
#pragma unroll
    for (int j = 0; j < 16; j++) ssum += __expf(z[j] - m);
    float lse = m + __logf(ssum);
#pragma unroll
    for (int j = 0; j < 16; j++) out[(size_t)row * 16 + j] = z[j] - lse;
}

// ---------------- launch ----------------

extern "C" void kernel_launch(void* const* d_in, const int* in_sizes, int n_in,
                              void* d_out, int out_size) {
    const float* x  = (const float*)d_in[0];
    const int*   ei = (const int*)d_in[1];
    const float* W1 = (const float*)d_in[2];
    const float* b1 = (const float*)d_in[3];
    const float* W2 = (const float*)d_in[4];
    const float* b2 = (const float*)d_in[5];
    const float* W3 = (const float*)d_in[6];
    const float* b3 = (const float*)d_in[7];
    float* out = (float*)d_out;

    int n = in_sizes[0] / 64;
    int e = in_sizes[1] / 2;
    const int* src = ei;
    const int* dst = ei + e;
    int write_h = (out_size >= n * 80) ? 1 : 0;

    void* cnt_p;  cudaGetSymbolAddress(&cnt_p,  g_count);
    void* flag_p; cudaGetSymbolAddress(&flag_p, g_flag);
    __half* G = nullptr; cudaGetSymbolAddress((void**)&G,  g_Gh);
    float* S1 = nullptr; cudaGetSymbolAddress((void**)&S1, g_S1);
    float* S2 = nullptr; cudaGetSymbolAddress((void**)&S2, g_S2);

    int nb = (n + 4095) / 4096;
    int e4blocks = ((e + 3) / 4 + 255) / 256;

    cudaMemsetAsync(cnt_p,  0, (size_t)n * sizeof(int));
    cudaMemsetAsync(flag_p, 0, 32 * sizeof(int));
    k_count<<<e4blocks, 256>>>(dst, e);
    k_scan<<<nb, 1024>>>(n);
    k_fill<<<e4blocks, 256>>>(src, dst, e);

    k_gemm64<<<592, 256>>>(x, W1, G, n, 0);
    k_agg<<<(n * 32 + 255) / 256, 256>>>(G, b1, S1, n);
    k_gemm64<<<592, 256>>>(S1, W2, G, n, 1);
    k_agg<<<(n * 32 + 255) / 256, 256>>>(G, b2, S2, n);
    k_final<<<(n + 255) / 256, 256>>>(S2, W3, b3, out, n, write_h);
}

// round 5
// speedup vs baseline: 1.4901x; 1.1213x over previous
#include <cuda_runtime.h>
#include <cuda_fp16.h>
#include <math.h>

// 3-layer GCN. Pull-style aggregation over a per-launch CSR (no feature atomics).
//   G(half) = (dis * act(X)) @ W      [W-in-registers f32x2 GEMM]
//   S[i] = b + dis[i] * (G[i] + sum_{dst=i} G[src])   (fp32 accum)
//   out = log_softmax(relu(S2) @ W3 + b3), plus h = relu(S2)

#define MAX_N 100000
#define MAX_E 1600000
#define NPAD  100352

__device__ int    g_count[NPAD];
__device__ int    g_rowstart[NPAD];
__device__ int    g_cursor[NPAD];
__device__ float  g_dis[NPAD];
__device__ int    g_sums[32];
__device__ int    g_flag[32];
__device__ int    g_esrc[MAX_E];
__device__ __half g_Gh[MAX_N * 64];
__device__ float  g_S1[MAX_N * 64];
__device__ float  g_S2[MAX_N * 64];

typedef unsigned long long ull;

__device__ __forceinline__ void ffma2(ull& acc, ull x, ull w) {
    asm("fma.rn.f32x2 %0, %1, %2, %0;" : "+l"(acc) : "l"(x), "l"(w));
}
__device__ __forceinline__ void fadd2(ull& a, ull b) {
    asm("add.rn.f32x2 %0, %0, %1;" : "+l"(a) : "l"(b));
}
__device__ __forceinline__ ull pack_dup(float v) {
    ull r;
    asm("mov.b64 %0, {%1, %1};" : "=l"(r) : "r"(__float_as_uint(v)));
    return r;
}
__device__ __forceinline__ ull h2_to_f2(unsigned int h) {
    __half2 hh = *reinterpret_cast<__half2*>(&h);
    float2 f = __half22float2(hh);
    return *reinterpret_cast<ull*>(&f);
}

// ---------------- CSR build ----------------

__global__ void k_count(const int* __restrict__ dst, int e) {
    int i4 = (blockIdx.x * blockDim.x + threadIdx.x) * 4;
    if (i4 + 3 < e) {
        int4 d = *(const int4*)&dst[i4];
        atomicAdd(&g_count[d.x], 1);
        atomicAdd(&g_count[d.y], 1);
        atomicAdd(&g_count[d.z], 1);
        atomicAdd(&g_count[d.w], 1);
    } else {
        for (int i = i4; i < e; i++) atomicAdd(&g_count[dst[i]], 1);
    }
}

// Single-kernel exclusive scan over counts (all nb<=25 blocks resident).
__global__ void k_scan(int n) {
    __shared__ int sh[1024];
    __shared__ int s_prev;
    int b = blockIdx.x, t = threadIdx.x;
    int base = b * 4096 + t * 4;
    int v0 = 0, v1 = 0, v2 = 0, v3 = 0;
    if (base + 3 < n) {
        int4 v = *(const int4*)&g_count[base];
        v0 = v.x; v1 = v.y; v2 = v.z; v3 = v.w;
    } else {
        if (base     < n) v0 = g_count[base];
        if (base + 1 < n) v1 = g_count[base + 1];
        if (base + 2 < n) v2 = g_count[base + 2];
    }
    int local = v0 + v1 + v2 + v3;
    sh[t] = local;
    __syncthreads();
    for (int off = 1; off < 1024; off <<= 1) {
        int x = (t >= off) ? sh[t - off] : 0;
        __syncthreads();
        sh[t] += x;
        __syncthreads();
    }
    if (t == 1023) {
        g_sums[b] = sh[1023];
        __threadfence();
        atomicExch(&g_flag[b], 1);
    }
    if (t < 32) {
        int p = 0;
        for (int i = t; i < b; i += 32) {
            while (atomicAdd(&g_flag[i], 0) == 0) { }
            p += atomicAdd(&g_sums[i], 0);
        }
#pragma unroll
        for (int o = 16; o; o >>= 1) p += __shfl_xor_sync(0xffffffffu, p, o);
        if (t == 0) s_prev = p;
    }
    int excl = sh[t] - local;
    __syncthreads();
    int run = s_prev + excl;
    if (base < n) {
        g_rowstart[base] = run; g_cursor[base] = run;
        g_dis[base] = rsqrtf((float)(v0 + 1)); run += v0;
    }
    if (base + 1 < n) {
        g_rowstart[base + 1] = run; g_cursor[base + 1] = run;
        g_dis[base + 1] = rsqrtf((float)(v1 + 1)); run += v1;
    }
    if (base + 2 < n) {
        g_rowstart[base + 2] = run; g_cursor[base + 2] = run;
        g_dis[base + 2] = rsqrtf((float)(v2 + 1)); run += v2;
    }
    if (base + 3 < n) {
        g_rowstart[base + 3] = run; g_cursor[base + 3] = run;
        g_dis[base + 3] = rsqrtf((float)(v3 + 1));
    }
}

__global__ void k_fill(const int* __restrict__ src, const int* __restrict__ dst, int e) {
    int i4 = (blockIdx.x * blockDim.x + threadIdx.x) * 4;
    if (i4 + 3 < e) {
        int4 s = *(const int4*)&src[i4];
        int4 d = *(const int4*)&dst[i4];
        g_esrc[atomicAdd(&g_cursor[d.x], 1)] = s.x;
        g_esrc[atomicAdd(&g_cursor[d.y], 1)] = s.y;
        g_esrc[atomicAdd(&g_cursor[d.z], 1)] = s.z;
        g_esrc[atomicAdd(&g_cursor[d.w], 1)] = s.w;
    } else {
        for (int i = i4; i < e; i++)
            g_esrc[atomicAdd(&g_cursor[dst[i]], 1)] = src[i];
    }
}

// ---------------- GEMM: G(half)[row] = (dis[row]*act(X[row])) @ W ----------------
// W lives in registers: thread owns cols (2*lane, 2*lane+1) for all 64 k
// (float2 wf[64], loaded once per block). X tile (64 rows) staged transposed,
// relu'd and dis-scaled in smem. Warp wid owns rows wid*8..wid*8+7; per k:
// 2 broadcast LDS.128 (row pairs) + 4 dup-movs + 8 FFMA2. fma-pipe bound.
// Persistent grid (1 block/SM); next tile's X prefetched into regs during compute.

__global__ void __launch_bounds__(256)
k_gemm64(const float* __restrict__ X, const float* __restrict__ W,
         __half* __restrict__ G, int n, int relu_in) {
    __shared__ float xst[64 * 64];   // 16 KB  xst[k*64 + r], dis-scaled

    int tid  = threadIdx.x;
    int lane = tid & 31;
    int wid  = tid >> 5;
    int r0   = wid * 8;

    // W columns (2*lane, 2*lane+1) for all k, in registers (128 regs).
    float2 wf[64];
    const float2* Wv = (const float2*)W;
#pragma unroll
    for (int k = 0; k < 64; k++) wf[k] = Wv[k * 32 + lane];

    int ntiles = (n + 63) >> 6;
    const float4* Xv = (const float4*)X;

    int r   = tid & 63;   // staging: this thread's row within tile
    int kgb = tid >> 6;   // staging: base float4-group (0..3)

    float4 pv[4];
    float  pd = 0.f;

    // prefetch first tile
    {
        int row = (blockIdx.x << 6) + r;
        if (row < n) {
            pd = g_dis[row];
#pragma unroll
            for (int j = 0; j < 4; j++) pv[j] = Xv[(size_t)row * 16 + kgb + 4 * j];
        } else {
            pd = 0.f;
#pragma unroll
            for (int j = 0; j < 4; j++) pv[j] = make_float4(0.f, 0.f, 0.f, 0.f);
        }
    }

    __half2* Gv = (__half2*)G;

    for (int tile = blockIdx.x; tile < ntiles; tile += gridDim.x) {
        int rowbase = tile << 6;
        __syncthreads();   // previous compute done; xst reusable
#pragma unroll
        for (int j = 0; j < 4; j++) {
            float4 v = pv[j];
            if (relu_in) {
                v.x = fmaxf(v.x, 0.f); v.y = fmaxf(v.y, 0.f);
                v.z = fmaxf(v.z, 0.f); v.w = fmaxf(v.w, 0.f);
            }
            int kg = kgb + 4 * j;
            xst[(4 * kg + 0) * 64 + r] = v.x * pd;
            xst[(4 * kg + 1) * 64 + r] = v.y * pd;
            xst[(4 * kg + 2) * 64 + r] = v.z * pd;
            xst[(4 * kg + 3) * 64 + r] = v.w * pd;
        }
        __syncthreads();   // tile staged

        // prefetch next tile while computing
        int tn = tile + gridDim.x;
        if (tn < ntiles) {
            int row = (tn << 6) + r;
            if (row < n) {
                pd = g_dis[row];
#pragma unroll
                for (int j = 0; j < 4; j++) pv[j] = Xv[(size_t)row * 16 + kgb + 4 * j];
            } else {
                pd = 0.f;
#pragma unroll
                for (int j = 0; j < 4; j++) pv[j] = make_float4(0.f, 0.f, 0.f, 0.f);
            }
        }

        ull a00 = 0, a01 = 0, a10 = 0, a11 = 0, a20 = 0, a21 = 0, a30 = 0, a31 = 0;
#pragma unroll
        for (int k = 0; k < 64; k++) {
            ulonglong2 xa = *(const ulonglong2*)&xst[k * 64 + r0];
            ulonglong2 xb = *(const ulonglong2*)&xst[k * 64 + r0 + 4];
            ull wx = pack_dup(wf[k].x);
            ull wy = pack_dup(wf[k].y);
            ffma2(a00, xa.x, wx); ffma2(a01, xa.x, wy);
            ffma2(a10, xa.y, wx); ffma2(a11, xa.y, wy);
            ffma2(a20, xb.x, wx); ffma2(a21, xb.x, wy);
            ffma2(a30, xb.y, wx); ffma2(a31, xb.y, wy);
        }

        ull ac[4][2] = {{a00, a01}, {a10, a11}, {a20, a21}, {a30, a31}};
#pragma unroll
        for (int rp = 0; rp < 4; rp++) {
            float2 c0 = *reinterpret_cast<float2*>(&ac[rp][0]);
            float2 c1 = *reinterpret_cast<float2*>(&ac[rp][1]);
            int re = rowbase + r0 + 2 * rp;
            if (re < n)     Gv[(size_t)re * 32 + lane]       = __floats2half2_rn(c0.x, c1.x);
            if (re + 1 < n) Gv[(size_t)(re + 1) * 32 + lane] = __floats2half2_rn(c0.y, c1.y);
        }
    }
}

// ---------------- Aggregation: 1 warp/node; 8 lanes x 16B, 4-edge ILP ----------------

__global__ void k_agg(const __half* __restrict__ G, const float* __restrict__ bias,
                      float* __restrict__ S, int n) {
    int warp = (blockIdx.x * blockDim.x + threadIdx.x) >> 5;
    if (warp >= n) return;
    int node = warp;
    int lane = threadIdx.x & 31;
    int q  = lane & 7;    // 16-byte feature chunk (8 halves)
    int pe = lane >> 3;   // 0..3 edge phase

    const uint4* __restrict__ Gv = (const uint4*)G;
    ull acc0 = 0, acc1 = 0, acc2 = 0, acc3 = 0;

    if (pe == 0) {
        uint4 v = Gv[(size_t)node * 8 + q];   // self-loop term
        acc0 = h2_to_f2(v.x); acc1 = h2_to_f2(v.y);
        acc2 = h2_to_f2(v.z); acc3 = h2_to_f2(v.w);
    }

    int s   = g_rowstart[node];
    int end = s + g_count[node];
    for (int p = s + pe; p < end; p += 4) {
        int j = g_esrc[p];
        uint4 v = Gv[(size_t)j * 8 + q];
        fadd2(acc0, h2_to_f2(v.x));
        fadd2(acc1, h2_to_f2(v.y));
        fadd2(acc2, h2_to_f2(v.z));
        fadd2(acc3, h2_to_f2(v.w));
    }

#pragma unroll
    for (int o = 8; o <= 16; o <<= 1) {
        fadd2(acc0, __shfl_xor_sync(0xffffffffu, acc0, o));
        fadd2(acc1, __shfl_xor_sync(0xffffffffu, acc1, o));
        fadd2(acc2, __shfl_xor_sync(0xffffffffu, acc2, o));
        fadd2(acc3, __shfl_xor_sync(0xffffffffu, acc3, o));
    }

    if (pe == 0) {
        float d = g_dis[node];
        float2 f0 = *reinterpret_cast<float2*>(&acc0);
        float2 f1 = *reinterpret_cast<float2*>(&acc1);
        float2 f2 = *reinterpret_cast<float2*>(&acc2);
        float2 f3 = *reinterpret_cast<float2*>(&acc3);
        const float4* Bv = (const float4*)bias;
        float4 b0 = Bv[q * 2], b1 = Bv[q * 2 + 1];
        float4 o0, o1;
        o0.x = fmaf(d, f0.x, b0.x); o0.y = fmaf(d, f0.y, b0.y);
        o0.z = fmaf(d, f1.x, b0.z); o0.w = fmaf(d, f1.y, b0.w);
        o1.x = fmaf(d, f2.x, b1.x); o1.y = fmaf(d, f2.y, b1.y);
        o1.z = fmaf(d, f3.x, b1.z); o1.w = fmaf(d, f3.y, b1.w);
        float4* Sv = (float4*)S;
        Sv[(size_t)node * 16 + q * 2]     = o0;
        Sv[(size_t)node * 16 + q * 2 + 1] = o1;
    }
}

// ---------------- Final: h = relu(S2); z = h@W3 + b3; log_softmax ----------------

__global__ void k_final(const float* __restrict__ S2, const float* __restrict__ W3,
                        const float* __restrict__ b3, float* __restrict__ out,
                        int n, int write_h) {
    __shared__ float w3s[64 * 16];
    __shared__ float b3s[16];
    for (int i = threadIdx.x; i < 64 * 16; i += blockDim.x) w3s[i] = W3[i];
    if (threadIdx.x < 16) b3s[threadIdx.x] = b3[threadIdx.x];
    __syncthreads();

    int row = blockIdx.x * blockDim.x + threadIdx.x;
    if (row >= n) return;

    float h[64];
    const float4* Sv = (const float4*)(S2 + (size_t)row * 64);
#pragma unroll
    for (int i = 0; i < 16; i++) {
        float4 v = Sv[i];
        h[4 * i + 0] = fmaxf(v.x, 0.0f);
        h[4 * i + 1] = fmaxf(v.y, 0.0f);
        h[4 * i + 2] = fmaxf(v.z, 0.0f);
        h[4 * i + 3] = fmaxf(v.w, 0.0f);
    }

    if (write_h) {
        float4* Hv = (float4*)(out + (size_t)n * 16 + (size_t)row * 64);
#pragma unroll
        for (int i = 0; i < 16; i++) {
            float4 v;
            v.x = h[4 * i + 0]; v.y = h[4 * i + 1];
            v.z = h[4 * i + 2]; v.w = h[4 * i + 3];
            Hv[i] = v;
        }
    }

    float z[16];
#pragma unroll
    for (int j = 0; j < 16; j++) z[j] = b3s[j];
#pragma unroll
    for (int k = 0; k < 64; k++) {
        float xv = h[k];
#pragma unroll
        for (int j = 0; j < 16; j++) z[j] = fmaf(xv, w3s[k * 16 + j], z[j]);
    }

    float m = z[0];
#pragma unroll
    for (int j = 1; j < 16; j++) m = fmaxf(m, z[j]);
    float ssum = 0.0f;
#pragma unroll
    for (int j = 0; j < 16; j++) ssum += __expf(z[j] - m);
    float lse = m + __logf(ssum);
#pragma unroll
    for (int j = 0; j < 16; j++) out[(size_t)row * 16 + j] = z[j] - lse;
}

// ---------------- launch ----------------

extern "C" void kernel_launch(void* const* d_in, const int* in_sizes, int n_in,
                              void* d_out, int out_size) {
    const float* x  = (const float*)d_in[0];
    const int*   ei = (const int*)d_in[1];
    const float* W1 = (const float*)d_in[2];
    const float* b1 = (const float*)d_in[3];
    const float* W2 = (const float*)d_in[4];
    const float* b2 = (const float*)d_in[5];
    const float* W3 = (const float*)d_in[6];
    const float* b3 = (const float*)d_in[7];
    float* out = (float*)d_out;

    int n = in_sizes[0] / 64;
    int e = in_sizes[1] / 2;
    const int* src = ei;
    const int* dst = ei + e;
    int write_h = (out_size >= n * 80) ? 1 : 0;

    void* cnt_p;  cudaGetSymbolAddress(&cnt_p,  g_count);
    void* flag_p; cudaGetSymbolAddress(&flag_p, g_flag);
    __half* G = nullptr; cudaGetSymbolAddress((void**)&G,  g_Gh);
    float* S1 = nullptr; cudaGetSymbolAddress((void**)&S1, g_S1);
    float* S2 = nullptr; cudaGetSymbolAddress((void**)&S2, g_S2);

    int nb = (n + 4095) / 4096;
    int e4blocks = ((e + 3) / 4 + 255) / 256;

    cudaMemsetAsync(cnt_p,  0, (size_t)n * sizeof(int));
    cudaMemsetAsync(flag_p, 0, 32 * sizeof(int));
    k_count<<<e4blocks, 256>>>(dst, e);
    k_scan<<<nb, 1024>>>(n);
    k_fill<<<e4blocks, 256>>>(src, dst, e);

    k_gemm64<<<148, 256>>>(x, W1, G, n, 0);
    k_agg<<<(n * 32 + 255) / 256, 256>>>(G, b1, S1, n);
    k_gemm64<<<148, 256>>>(S1, W2, G, n, 1);
    k_agg<<<(n * 32 + 255) / 256, 256>>>(G, b2, S2, n);
    k_final<<<(n + 255) / 256, 256>>>(S2, W3, b3, out, n, write_h);
}